// round 1
// baseline (speedup 1.0000x reference)
#include <cuda_runtime.h>

// CRF forward (alpha) recursion on GB300.
// B independent batches; T sequential steps; L=64 tags.
// Per batch: 4 warps, prev-dimension split 4-way, E matrix in registers,
// p broadcast by intra-warp shuffles, partial sums exchanged via smem with
// one named barrier per step (double-buffered). 2 batches per 256-thread CTA.

#define FULLMASK 0xffffffffu

__device__ __forceinline__ float ex2f_(float x) {
    float r; asm("ex2.approx.f32 %0, %1;" : "=f"(r) : "f"(x)); return r;
}
__device__ __forceinline__ float lg2f_(float x) {
    float r; asm("lg2.approx.f32 %0, %1;" : "=f"(r) : "f"(x)); return r;
}

__global__ __launch_bounds__(256, 1)
void crf_forward_kernel(const float* __restrict__ X,
                        const float* __restrict__ trans,
                        float* __restrict__ out,
                        int B, int T)
{
    constexpr float LOG2E = 1.4426950408889634f;
    constexpr float LN2   = 0.6931471805599453f;
    constexpr float NEG2  = -10000.0f * 1.4426950408889634f; // -10000 in base-2 units

    const int tid  = threadIdx.x;
    const int half = tid >> 7;        // which batch inside this CTA (0/1)
    const int t128 = tid & 127;
    const int w    = t128 >> 5;       // warp within the batch group: 0..3
    const int lane = tid & 31;
    const int b    = blockIdx.x * 2 + half;

    if (b >= B) return;               // whole 128-thread half exits together

    const int n0 = lane;              // first tag column owned by this thread
    const int n1 = lane + 32;         // second tag column

    // Partial-sum exchange buffers: [half][double-buffer][tag][warp]
    __shared__ __align__(16) float part[2][2][64][4];

    // ---- Prologue: load this thread's slice of exp2(transition) into registers.
    // Thread handles prev rows {i, i+32} for i in [8w, 8w+8), columns {n0, n1}.
    // Column B (nxt==0) is overridden to 1.0 so S[0] = sum_prev p[prev]; the
    // -10000 is re-applied as a constant after the log (matches reference).
    float eA[8], eB[8], eC[8], eD[8];
#pragma unroll
    for (int j = 0; j < 8; j++) {
        const int i = w * 8 + j;
        const float tA = trans[i * 64 + n0];
        const float tB = trans[i * 64 + n1];
        const float tC = trans[(i + 32) * 64 + n0];
        const float tD = trans[(i + 32) * 64 + n1];
        eA[j] = (n0 == 0) ? 1.0f : ex2f_(tA * LOG2E);
        eB[j] = ex2f_(tB * LOG2E);
        eC[j] = (n0 == 0) ? 1.0f : ex2f_(tC * LOG2E);
        eD[j] = ex2f_(tD * LOG2E);
    }

    // ---- Init: alpha = 0 at tag B(=0), -10000 elsewhere (base-2 units).
    float a0 = (n0 == 0) ? 0.0f : NEG2;
    float a1 = NEG2;
    float p0 = ex2f_(a0);
    float p1 = ex2f_(a1);
    float d  = 0.0f;   // lagged shift (= previous step's a[tag 2])
    float M  = 0.0f;   // accumulated shift (base-2)

    const float* __restrict__ xb = X + (size_t)b * (size_t)T * 64;
    float x0 = xb[n0];
    float x1 = xb[n1];

    const int barid = 1 + half;       // named barrier per batch half

    for (int t = 0; t < T; t++) {
        const int buf = t & 1;

        // ---- Matvec over this warp's 16 prev tags (E2 in registers).
        float s0a = 0.f, s0b = 0.f, s1a = 0.f, s1b = 0.f;
#pragma unroll
        for (int j = 0; j < 8; j++) {
            const int src = w * 8 + j;
            const float pi = __shfl_sync(FULLMASK, p0, src);   // p[i]
            const float pj = __shfl_sync(FULLMASK, p1, src);   // p[i+32]
            s0a = fmaf(pi, eA[j], s0a);
            s1a = fmaf(pi, eB[j], s1a);
            s0b = fmaf(pj, eC[j], s0b);
            s1b = fmaf(pj, eD[j], s1b);
        }
        part[half][buf][n0][w] = s0a + s0b;
        part[half][buf][n1][w] = s1a + s1b;

        // Prefetch next step's emissions (L2-resident after warmup).
        float nx0 = 0.f, nx1 = 0.f;
        if (t + 1 < T) {
            nx0 = xb[(t + 1) * 64 + n0];
            nx1 = xb[(t + 1) * 64 + n1];
        }

        asm volatile("bar.sync %0, 128;" :: "r"(barid) : "memory");

        // ---- Combine 4 warp-partials, log, add emission, re-shift, exp.
        const float4 v0 = *(const float4*)&part[half][buf][n0][0];
        const float4 v1 = *(const float4*)&part[half][buf][n1][0];
        const float S0 = (v0.x + v0.y) + (v0.z + v0.w);
        const float S1 = (v1.x + v1.y) + (v1.z + v1.w);

        float r0 = fmaf(x0, LOG2E, lg2f_(S0));
        float r1 = fmaf(x1, LOG2E, lg2f_(S1));
        if (n0 == 0) r0 += NEG2;      // re-apply masked column into tag B

        a0 = r0 - d;
        a1 = r1 - d;
        M += d;
        p0 = ex2f_(a0);
        p1 = ex2f_(a1);
        d  = __shfl_sync(FULLMASK, a0, 2);   // next step's shift (off critical path)

        x0 = nx0;
        x1 = nx1;
    }

    // ---- Epilogue: un-shift, convert base-2 -> natural log. Warp 0 writes.
    if (w == 0) {
        out[(size_t)b * 64 + n0] = (a0 + M) * LN2;
        out[(size_t)b * 64 + n1] = (a1 + M) * LN2;
    }
}

extern "C" void kernel_launch(void* const* d_in, const int* in_sizes, int n_in,
                              void* d_out, int out_size)
{
    const float* X     = (const float*)d_in[0];
    const float* trans = (const float*)d_in[1];
    float* out = (float*)d_out;

    // L = 64 (transition is 64x64 = 4096 elements).
    const int B = out_size / 64;                 // 256
    const int T = in_sizes[0] / (B * 64);        // 512

    const int blocks = (B + 1) / 2;              // 2 batches per CTA
    crf_forward_kernel<<<blocks, 256>>>(X, trans, out, B, T);
}

// round 2
// speedup vs baseline: 1.1129x; 1.1129x over previous
#include <cuda_runtime.h>

// CRF forward recursion, exp2-domain with lagged renormalization.
// Layout: CTA = 128 threads = 4 warps, handles TWO batches (dual chain per
// thread, shared E2 registers). Warp w owns nxt-columns [16w,16w+16); lanes
// l and l+16 split the 64-long prev reduction (halves 0/1), combined with one
// butterfly shuffle. The p = exp2(alpha) vector lives in double-buffered smem
// (broadcast LDS.128 reads, padded to avoid bank conflicts). Exactly ONE
// __syncthreads per timestep.

#define FULLMASK 0xffffffffu

__device__ __forceinline__ float ex2f_(float x) {
    float r; asm("ex2.approx.f32 %0, %1;" : "=f"(r) : "f"(x)); return r;
}
__device__ __forceinline__ float lg2f_(float x) {
    float r; asm("lg2.approx.f32 %0, %1;" : "=f"(r) : "f"(x)); return r;
}

// p-vector index with +16B pad between halves: 0..31 -> 0..31, 32..63 -> 36..67
__device__ __forceinline__ int pidx(int i) { return i + ((i >> 5) << 2); }

__global__ __launch_bounds__(128, 1)
void crf_forward_kernel(const float* __restrict__ X,
                        const float* __restrict__ trans,
                        float* __restrict__ out,
                        int B, int T)
{
    constexpr float LOG2E = 1.4426950408889634f;
    constexpr float LN2   = 0.6931471805599453f;
    constexpr float NEG2  = -10000.0f * 1.4426950408889634f;

    const int tid  = threadIdx.x;
    const int w    = tid >> 5;
    const int lane = tid & 31;
    const int col  = (w << 4) | (lane & 15);  // owned nxt column (0..63)
    const int half = lane >> 4;               // prev half: 0 or 1

    const int b0 = blockIdx.x * 2;
    int b1 = b0 + 1; if (b1 >= B) b1 = b0;    // defensive (B is even here)

    // p buffers: [double-buffer][batch][padded 64 floats]
    __shared__ __align__(16) float pbuf[2][2][72];
    __shared__ float dslot[2][2];             // lagged shift per batch

    // ---- E2 slice: 32 prev rows (this half) for this column, in registers.
    // Column 0 (tag 'B', masked to -1e4 in trans) is overridden to 1.0; the
    // -1e4 is re-applied as a constant after the log (algebraically identical).
    float e[32];
#pragma unroll
    for (int j = 0; j < 32; j++) {
        const float tv = trans[(half * 32 + j) * 64 + col];
        e[j] = (col == 0) ? 1.0f : ex2f_(tv * LOG2E);
    }

    // ---- init: p = exp2(alpha_init) = (1,0,0,...,0)
    if (lane < 16) {
        const float pi = (col == 0) ? 1.0f : 0.0f;
        pbuf[0][0][pidx(col)] = pi;
        pbuf[0][1][pidx(col)] = pi;
    }
    if (tid == 0) { dslot[0][0] = 0.0f; dslot[0][1] = 0.0f; }

    const float* __restrict__ xA = X + (size_t)b0 * T * 64;
    const float* __restrict__ xB = X + (size_t)b1 * T * 64;
    float xa = xA[col];
    float xb = xB[col];
    float MA = 0.f, MB = 0.f, aA = 0.f, aB = 0.f;

    __syncthreads();

    const int pbase = pidx(half * 32);        // 0 or 36 (16B-aligned)

    for (int t = 0; t < T; t++) {
        const int cur = t & 1, nxt = cur ^ 1;

        // lagged shifts (broadcast LDS, ready well before use)
        const float dA = dslot[cur][0];
        const float dB = dslot[cur][1];

        // prefetch next emissions (overlaps the whole step)
        float nxa = 0.f, nxb = 0.f;
        if (t + 1 < T) {
            nxa = xA[(t + 1) * 64 + col];
            nxb = xB[(t + 1) * 64 + col];
        }

        // ---- half-matvec: 32 prev values from smem, E2 in registers
        float s0A=0.f,s1A=0.f,s2A=0.f,s3A=0.f;
        float s0B=0.f,s1B=0.f,s2B=0.f,s3B=0.f;
#pragma unroll
        for (int k = 0; k < 8; k++) {
            const float4 pa = *(const float4*)&pbuf[cur][0][pbase + 4*k];
            const float4 pb = *(const float4*)&pbuf[cur][1][pbase + 4*k];
            s0A = fmaf(pa.x, e[4*k+0], s0A);
            s1A = fmaf(pa.y, e[4*k+1], s1A);
            s2A = fmaf(pa.z, e[4*k+2], s2A);
            s3A = fmaf(pa.w, e[4*k+3], s3A);
            s0B = fmaf(pb.x, e[4*k+0], s0B);
            s1B = fmaf(pb.y, e[4*k+1], s1B);
            s2B = fmaf(pb.z, e[4*k+2], s2B);
            s3B = fmaf(pb.w, e[4*k+3], s3B);
        }
        float SA = (s0A + s1A) + (s2A + s3A);
        float SB = (s0B + s1B) + (s2B + s3B);
        SA += __shfl_xor_sync(FULLMASK, SA, 16);   // combine prev halves
        SB += __shfl_xor_sync(FULLMASK, SB, 16);

        // ---- epilogue: log, emission, mask, re-shift, exp
        float rA = fmaf(xa, LOG2E, lg2f_(SA));
        float rB = fmaf(xb, LOG2E, lg2f_(SB));
        if (col == 0) { rA += NEG2; rB += NEG2; }

        aA = rA - dA;  MA += dA;
        aB = rB - dB;  MB += dB;
        const float pA_ = ex2f_(aA);
        const float pB_ = ex2f_(aB);

        if (lane < 16) {
            pbuf[nxt][0][pidx(col)] = pA_;
            pbuf[nxt][1][pidx(col)] = pB_;
        }
        if (tid == 2) {               // col==2: next step's shift
            dslot[nxt][0] = aA;
            dslot[nxt][1] = aB;
        }

        xa = nxa; xb = nxb;
        __syncthreads();
    }

    if (lane < 16) {
        out[(size_t)b0 * 64 + col] = (aA + MA) * LN2;
        out[(size_t)b1 * 64 + col] = (aB + MB) * LN2;
    }
}

extern "C" void kernel_launch(void* const* d_in, const int* in_sizes, int n_in,
                              void* d_out, int out_size)
{
    const float* X     = (const float*)d_in[0];
    const float* trans = (const float*)d_in[1];
    float* out = (float*)d_out;

    const int B = out_size / 64;              // 256
    const int T = in_sizes[0] / (B * 64);     // 512

    const int blocks = (B + 1) / 2;           // 2 batches per 128-thread CTA
    crf_forward_kernel<<<blocks, 128>>>(X, trans, out, B, T);
}